// round 15
// baseline (speedup 1.0000x reference)
#include <cuda_runtime.h>
#include <cuda_bf16.h>
#include <stdint.h>

// Problem constants (reference: N=2048, NUM_COLORS=16, x in [0,16))
#define NN     2048
#define NSH    11            // log2(NN)
#define NC     16
#define CELLS  (NN*NN)       // 4,194,304
#define GRID_S 512           // slow-path grid (148 SMs x 4 blocks = 592 >= 512)
#define CHUNK  (CELLS/GRID_S)// 8192 cells per slow block

// dtype modes
#define MODE_I64  0
#define MODE_I32  1
#define MODE_F32  2
#define MODE_F64  3
#define MODE_BF16 4

// ---------------- scratch (static __device__ arrays; no allocs) ----------------
static __device__ unsigned char      g_x8[CELLS];                 // 4 MB
static __device__ int                g_rowhist[NN*NC];
static __device__ int                g_colhist[NN*NC];
static __device__ unsigned long long g_hash[2*NN];
static __device__ unsigned long long g_htab[8192];                // dup-check table (2 x 4096)
static __device__ int                g_rclass[NN];
static __device__ int                g_cclass[NN];
static __device__ unsigned int       g_table[NC*CELLS];           // 256 MB (slow path only)
static __device__ int                g_scan[CELLS];
static __device__ int                g_bsums[GRID_S];
static __device__ unsigned int       g_sync[8];                   // monotonic slow-path barriers
static __device__ unsigned int       g_ccnt[8];                   // monotonic colhist group counters
static __device__ int                g_fast;

// ---------------- helpers ----------------
__device__ __forceinline__ int hw_ok(unsigned h) {
    return h == 0u || (h >= 0x3F80u && h <= 0x4170u);
}
__device__ int detect_mode(const unsigned* __restrict__ x, int t, int* bad) {
    if (t < 5) bad[t] = 0;
    __syncthreads();
    unsigned w0 = x[2*t], w1 = x[2*t+1];
    if (!(w1 == 0u && w0 < 16u))                         bad[MODE_I64] = 1;
    if (!(w0 < 16u && w1 < 16u))                         bad[MODE_I32] = 1;
    int f0 = (w0 == 0u) || (((w0 & 0xFFFFu) == 0u) && hw_ok(w0 >> 16));
    int f1 = (w1 == 0u) || (((w1 & 0xFFFFu) == 0u) && hw_ok(w1 >> 16));
    if (!(f0 && f1))                                     bad[MODE_F32] = 1;
    if (!(w0 == 0u && (w1 == 0u || (w1 >= 0x3FF00000u && w1 <= 0x402E0000u))))
                                                         bad[MODE_F64] = 1;
    if (!(hw_ok(w0 & 0xFFFFu) && hw_ok(w0 >> 16) &&
          hw_ok(w1 & 0xFFFFu) && hw_ok(w1 >> 16)))       bad[MODE_BF16] = 1;
    __syncthreads();
    if      (!bad[MODE_I64])  return MODE_I64;
    else if (!bad[MODE_I32])  return MODE_I32;
    else if (!bad[MODE_F64])  return MODE_F64;
    else if (!bad[MODE_F32])  return MODE_F32;
    else if (!bad[MODE_BF16]) return MODE_BF16;
    return MODE_I32;
}
__device__ __forceinline__ unsigned long long fnv16_sm(const int* h) {
    unsigned long long hv = 1469598103934665603ULL;
#pragma unroll
    for (int c = 0; c < NC; c++) { hv ^= (unsigned long long)(unsigned)h[c]; hv *= 1099511628211ULL; }
    return hv;
}
__device__ __forceinline__ unsigned long long fnv16_cg(const int* h) {
    unsigned long long hv = 1469598103934665603ULL;
#pragma unroll
    for (int c = 0; c < NC; c++) { hv ^= (unsigned long long)(unsigned)__ldcg(h + c); hv *= 1099511628211ULL; }
    return hv;
}
__device__ __forceinline__ unsigned cell_key(int p) {
    int i = p >> NSH, j = p & (NN-1);
    return ((unsigned)g_x8[p] << 22) | ((unsigned)__ldcg(&g_rclass[i]) << NSH)
                                     | (unsigned)__ldcg(&g_cclass[j]);
}

// ---------------- k_convert: detect + decode + ROW HIST + row hash + glue ----
// One block == one row (256 threads x 8 cells).
__global__ void k_convert(const void* __restrict__ xv) {
    __shared__ int bad[5];
    __shared__ int wb[8*NC];
    __shared__ int rh[NC];
    int t = threadIdx.x;
    int m = detect_mode((const unsigned*)xv, t, bad);
    int row = blockIdx.x;
    int gid = row*256 + t;
    // init glue (spread over early threads)
    if (gid == 0) g_fast = 1;
    if (gid < 8192) g_htab[gid] = 0ull;
    if (gid < NN*NC) g_colhist[gid] = 0;
    if (t < 8*NC) wb[t] = 0;
    __syncthreads();
    int base = gid*8;
    unsigned v[8];
    if (m == MODE_I32) {
        const int4* p = (const int4*)((const int*)xv + base);
        int4 a = p[0], b = p[1];
        v[0]=(unsigned)a.x&0xFu; v[1]=(unsigned)a.y&0xFu; v[2]=(unsigned)a.z&0xFu; v[3]=(unsigned)a.w&0xFu;
        v[4]=(unsigned)b.x&0xFu; v[5]=(unsigned)b.y&0xFu; v[6]=(unsigned)b.z&0xFu; v[7]=(unsigned)b.w&0xFu;
    } else if (m == MODE_F32) {
        const float4* p = (const float4*)((const float*)xv + base);
        float4 a = p[0], b = p[1];
        v[0]=(unsigned)(int)a.x&0xFu; v[1]=(unsigned)(int)a.y&0xFu; v[2]=(unsigned)(int)a.z&0xFu; v[3]=(unsigned)(int)a.w&0xFu;
        v[4]=(unsigned)(int)b.x&0xFu; v[5]=(unsigned)(int)b.y&0xFu; v[6]=(unsigned)(int)b.z&0xFu; v[7]=(unsigned)(int)b.w&0xFu;
    } else if (m == MODE_I64) {
        const unsigned* p = (const unsigned*)xv;
#pragma unroll
        for (int e = 0; e < 8; e++) v[e] = p[2*(base+e)] & 0xFu;
    } else if (m == MODE_F64) {
        const double* p = (const double*)xv;
#pragma unroll
        for (int e = 0; e < 8; e++) v[e] = (unsigned)(int)p[base+e] & 0xFu;
    } else { // BF16
        const unsigned short* p = (const unsigned short*)xv;
#pragma unroll
        for (int e = 0; e < 8; e++)
            v[e] = (unsigned)(int)__uint_as_float((unsigned)p[base+e] << 16) & 0xFu;
    }
    unsigned long long w = 0;
#pragma unroll
    for (int e = 0; e < 8; e++) w |= ((unsigned long long)v[e]) << (8*e);
    ((unsigned long long*)g_x8)[gid] = w;
    int wp = (t >> 5) * NC;
#pragma unroll
    for (int e = 0; e < 8; e++) atomicAdd(&wb[wp + (int)v[e]], 1);
    __syncthreads();
    if (t < NC) {
        int s = 0;
#pragma unroll
        for (int k = 0; k < 8; k++) s += wb[k*NC + t];
        g_rowhist[row*NC + t] = s;
        rh[t] = s;
    }
    __syncthreads();
    if (t == 0) g_hash[row] = fnv16_sm(rh);
}

// ---------------- k_colhist: 512 blocks (8 col groups x 64 row chunks) -------
// The 64th finishing block of a column group computes that group's hashes.
__global__ void k_colhist() {
    __shared__ unsigned char sb[NC*256];
    __shared__ int fin;
    int t = threadIdx.x;
#pragma unroll
    for (int c = 0; c < NC; c++) sb[c*256 + t] = 0;
    __syncthreads();
    int j  = blockIdx.x*256 + t;              // blockIdx.x in [0,8)
    int r0 = blockIdx.y * 32;                 // blockIdx.y in [0,64)
    for (int r = r0; r < r0 + 32; r++) {
        int v = g_x8[r*NN + j];
        sb[v*256 + t]++;
    }
#pragma unroll
    for (int c = 0; c < NC; c++) {
        int cnt = sb[c*256 + t];
        if (cnt) atomicAdd(&g_colhist[j*NC + c], cnt);
    }
    __threadfence();
    __syncthreads();
    if (t == 0) {
        unsigned old = atomicAdd(&g_ccnt[blockIdx.x], 1u);
        fin = ((old % 64u) == 63u);           // monotonic counter: replay-safe
    }
    __syncthreads();
    if (fin) {
        __threadfence();
        g_hash[NN + j] = fnv16_cg(&g_colhist[j*NC]);
    }
}

// ---------------- k_check: O(N) duplicate detection ----------------
// Insert all 2x2048 hashes into per-kind 4096-slot tables via atomicCAS.
// A repeated hash value => possible duplicate hist => take the exact slow path.
// (hist-equal => hash-equal, so the fast path is provably safe.)
__global__ void k_check() {
    int idx = blockIdx.x*1024 + threadIdx.x;  // 0..4095
    int isCol = idx >> 11, i = idx & (NN-1);
    unsigned long long h = __ldcg(&g_hash[isCol*NN + i]) | 1ull;  // nonzero sentinel
    unsigned long long* tab = g_htab + isCol*4096;
    unsigned slot = (unsigned)(h % 4096ull);
    for (;;) {
        unsigned long long old = atomicCAS(&tab[slot], 0ull, h);
        if (old == 0ull) break;               // inserted
        if (old == h) { g_fast = 0; break; }  // duplicate hash
        slot = (slot + 1u) & 4095u;
    }
}

// ---------------- k_slow: classes + table + scan + (slow) output -----------
// 512 blocks x 256 threads, <=64 regs, 4 blocks/SM guaranteed => co-resident.
__device__ __forceinline__ void gsync(int id) {
    __syncthreads();
    if (threadIdx.x == 0) {
        __threadfence();
        unsigned old = atomicAdd(&g_sync[id], 1u);
        unsigned target = old - (old % GRID_S) + GRID_S;
        while (*(volatile unsigned*)&g_sync[id] < target) { __nanosleep(64); }
        __threadfence();
    }
    __syncthreads();
}
__global__ void __launch_bounds__(256, 4) k_slow() {
    if (g_fast) return;
    __shared__ int red[256];
    __shared__ int ws[8], wo[8];
    int t = threadIdx.x, b = blockIdx.x;
    // phase -1: compute classes (8 units per block; O(i) scan, slow path only)
    for (int u = 0; u < 8; u++) {
        int unit = b*8 + u;
        int i = unit & (NN-1), isCol = unit >> 11;
        const unsigned long long* H = g_hash + isCol*NN;
        const int* hist = isCol ? g_colhist : g_rowhist;
        unsigned long long hi = __ldcg(&H[i]);
        int best = i;
        for (int j = t; j < i; j += 256) {
            if (__ldcg(&H[j]) == hi) {
                bool eq = true;
#pragma unroll
                for (int c = 0; c < NC; c++)
                    eq = eq && (__ldcg(&hist[j*NC + c]) == __ldcg(&hist[i*NC + c]));
                if (eq && j < best) best = j;
            }
        }
        red[t] = best;
        __syncthreads();
        for (int s = 128; s; s >>= 1) {
            if (t < s) red[t] = min(red[t], red[t+s]);
            __syncthreads();
        }
        if (t == 0) (isCol ? g_cclass : g_rclass)[i] = red[0];
        __syncthreads();
    }
    gsync(0);
    int cbase = b*CHUNK;
    // phase 0: reset touched table slots
    for (int p = cbase + t; p < cbase + CHUNK; p += 256)
        g_table[cell_key(p)] = 0xFFFFFFFFu;
    gsync(1);
    // phase 1: min row-major index per key
    for (int p = cbase + t; p < cbase + CHUNK; p += 256)
        atomicMin(&g_table[cell_key(p)], (unsigned)p);
    gsync(2);
    // phase 2: first-occurrence flags + per-block scan (2 sub-tiles of 4096)
    {
        int carry = 0;
        for (int sub = 0; sub < 2; sub++) {
            int base = cbase + sub*4096 + t*16;
            int f[16], s = 0;
#pragma unroll
            for (int e = 0; e < 16; e++) {
                int p = base + e;
                f[e] = (__ldcg(&g_table[cell_key(p)]) == (unsigned)p);
                s += f[e];
            }
            int lane = t & 31, warp = t >> 5;
            int v = s;
#pragma unroll
            for (int o = 1; o < 32; o <<= 1) {
                int nv = __shfl_up_sync(0xffffffffu, v, o);
                if (lane >= o) v += nv;
            }
            if (lane == 31) ws[warp] = v;
            __syncthreads();
            if (t < 8) {
                int w = ws[t];
#pragma unroll
                for (int o = 1; o < 8; o <<= 1) {
                    int nv = __shfl_up_sync(0xffu, w, o);
                    if (t >= o) w += nv;
                }
                wo[t] = w;
            }
            __syncthreads();
            int ex = (v - s) + (warp ? wo[warp-1] : 0);
            int run = carry + ex;
#pragma unroll
            for (int e = 0; e < 16; e++) { g_scan[base + e] = run; run += f[e]; }
            carry += wo[7];
            __syncthreads();
        }
        if (t == 0) g_bsums[b] = carry;
    }
    gsync(3);
    // phase 3: serial scan of 512 block sums
    if (b == 0 && t == 0) {
        int acc = 0;
        for (int q = 0; q < GRID_S; q++) {
            int s = g_bsums[q];
            g_bsums[q] = acc;
            acc += s;
        }
    }
    gsync(4);
}

// ---------------- k_out ----------------
__global__ void k_out(float* __restrict__ out) {
    int t = blockIdx.x*blockDim.x + threadIdx.x;   // 0 .. CELLS/8-1
    int base = t*8;
    float4 r0, r1;
    if (g_fast) {
        r0 = make_float4((float)base,     (float)(base+1), (float)(base+2), (float)(base+3));
        r1 = make_float4((float)(base+4), (float)(base+5), (float)(base+6), (float)(base+7));
    } else {
        float v[8];
#pragma unroll
        for (int e = 0; e < 8; e++) {
            unsigned q = g_table[cell_key(base + e)];
            v[e] = (float)(g_scan[q] + g_bsums[q >> 13]);
        }
        r0 = make_float4(v[0], v[1], v[2], v[3]);
        r1 = make_float4(v[4], v[5], v[6], v[7]);
    }
    float4* o = (float4*)(out + base);
    o[0] = r0;
    o[1] = r1;
}

// ---------------- launch (5 kernels) ----------------
extern "C" void kernel_launch(void* const* d_in, const int* in_sizes, int n_in,
                              void* d_out, int out_size) {
    const void* x = d_in[0];
    (void)in_sizes; (void)n_in; (void)out_size;

    k_convert <<<NN, 256>>>(x);
    k_colhist <<<dim3(8, 64), 256>>>();
    k_check   <<<4, 1024>>>();
    k_slow    <<<GRID_S, 256>>>();
    k_out     <<<CELLS/8/256, 256>>>((float*)d_out);
}

// round 16
// speedup vs baseline: 1.0300x; 1.0300x over previous
#include <cuda_runtime.h>
#include <cuda_bf16.h>
#include <stdint.h>

// Problem constants (reference: N=2048, NUM_COLORS=16, x in [0,16))
#define NN     2048
#define NSH    11            // log2(NN)
#define NC     16
#define CELLS  (NN*NN)       // 4,194,304
#define GRID_S 512           // slow-path grid (148 SMs x 4 blocks = 592 >= 512)
#define CHUNK  (CELLS/GRID_S)// 8192 cells per slow block

// dtype modes
#define MODE_I64  0
#define MODE_I32  1
#define MODE_F32  2
#define MODE_F64  3
#define MODE_BF16 4

// ---------------- scratch (static __device__ arrays; no allocs) ----------------
static __device__ unsigned char      g_x8[CELLS];                 // 4 MB
static __device__ int                g_rowhist[NN*NC];
static __device__ int                g_colhist[NN*NC];
static __device__ unsigned long long g_hash[2*NN];
static __device__ unsigned long long g_htab[8192];                // dup-check table (2 x 4096)
static __device__ int                g_rclass[NN];
static __device__ int                g_cclass[NN];
static __device__ unsigned int       g_table[NC*CELLS];           // 256 MB (slow path only)
static __device__ int                g_scan[CELLS];
static __device__ int                g_bsums[GRID_S];
static __device__ unsigned int       g_sync[8];                   // monotonic slow-path barriers
static __device__ unsigned int       g_ccnt[8];                   // colhist finisher counters
static __device__ int                g_fast;

// ---------------- helpers ----------------
__device__ __forceinline__ int hw_ok(unsigned h) {
    return h == 0u || (h >= 0x3F80u && h <= 0x4170u);
}
__device__ int detect_mode(const unsigned* __restrict__ x, int t, int* bad) {
    if (t < 5) bad[t] = 0;
    __syncthreads();
    unsigned w0 = x[2*t], w1 = x[2*t+1];
    if (!(w1 == 0u && w0 < 16u))                         bad[MODE_I64] = 1;
    if (!(w0 < 16u && w1 < 16u))                         bad[MODE_I32] = 1;
    int f0 = (w0 == 0u) || (((w0 & 0xFFFFu) == 0u) && hw_ok(w0 >> 16));
    int f1 = (w1 == 0u) || (((w1 & 0xFFFFu) == 0u) && hw_ok(w1 >> 16));
    if (!(f0 && f1))                                     bad[MODE_F32] = 1;
    if (!(w0 == 0u && (w1 == 0u || (w1 >= 0x3FF00000u && w1 <= 0x402E0000u))))
                                                         bad[MODE_F64] = 1;
    if (!(hw_ok(w0 & 0xFFFFu) && hw_ok(w0 >> 16) &&
          hw_ok(w1 & 0xFFFFu) && hw_ok(w1 >> 16)))       bad[MODE_BF16] = 1;
    __syncthreads();
    if      (!bad[MODE_I64])  return MODE_I64;
    else if (!bad[MODE_I32])  return MODE_I32;
    else if (!bad[MODE_F64])  return MODE_F64;
    else if (!bad[MODE_F32])  return MODE_F32;
    else if (!bad[MODE_BF16]) return MODE_BF16;
    return MODE_I32;
}
__device__ __forceinline__ unsigned long long fnv16_sm(const int* h) {
    unsigned long long hv = 1469598103934665603ULL;
#pragma unroll
    for (int c = 0; c < NC; c++) { hv ^= (unsigned long long)(unsigned)h[c]; hv *= 1099511628211ULL; }
    return hv;
}
__device__ __forceinline__ unsigned long long fnv16_cg(const int* h) {
    unsigned long long hv = 1469598103934665603ULL;
#pragma unroll
    for (int c = 0; c < NC; c++) { hv ^= (unsigned long long)(unsigned)__ldcg(h + c); hv *= 1099511628211ULL; }
    return hv;
}
// Insert a hash into the per-kind CAS table; duplicate => clear g_fast.
__device__ __forceinline__ void dup_insert(unsigned long long h, int isCol) {
    h |= 1ull;                                 // nonzero sentinel
    unsigned long long* tab = g_htab + isCol*4096;
    unsigned slot = (unsigned)(h % 4096ull);
    for (;;) {
        unsigned long long old = atomicCAS(&tab[slot], 0ull, h);
        if (old == 0ull) break;
        if (old == h) { g_fast = 0; break; }
        slot = (slot + 1u) & 4095u;
    }
}
__device__ __forceinline__ unsigned cell_key(int p) {
    int i = p >> NSH, j = p & (NN-1);
    return ((unsigned)g_x8[p] << 22) | ((unsigned)__ldcg(&g_rclass[i]) << NSH)
                                     | (unsigned)__ldcg(&g_cclass[j]);
}

// ---------------- k_convert: detect + decode + ROW HIST + row hash + glue ----
// One block == one row (256 threads x 8 cells). R13 body.
__global__ void k_convert(const void* __restrict__ xv) {
    __shared__ int bad[5];
    __shared__ int wb[8*NC];
    __shared__ int rh[NC];
    int t = threadIdx.x;
    int m = detect_mode((const unsigned*)xv, t, bad);
    int row = blockIdx.x;
    int gid = row*256 + t;
    if (gid == 0) g_fast = 1;
    if (gid < 8)  g_ccnt[gid] = 0;
    if (gid < 8192) g_htab[gid] = 0ull;
    if (gid < NN*NC) g_colhist[gid] = 0;
    if (t < 8*NC) wb[t] = 0;
    __syncthreads();
    int base = gid*8;
    unsigned v[8];
    if (m == MODE_I32) {
        const int4* p = (const int4*)((const int*)xv + base);
        int4 a = p[0], b = p[1];
        v[0]=(unsigned)a.x&0xFu; v[1]=(unsigned)a.y&0xFu; v[2]=(unsigned)a.z&0xFu; v[3]=(unsigned)a.w&0xFu;
        v[4]=(unsigned)b.x&0xFu; v[5]=(unsigned)b.y&0xFu; v[6]=(unsigned)b.z&0xFu; v[7]=(unsigned)b.w&0xFu;
    } else if (m == MODE_F32) {
        const float4* p = (const float4*)((const float*)xv + base);
        float4 a = p[0], b = p[1];
        v[0]=(unsigned)(int)a.x&0xFu; v[1]=(unsigned)(int)a.y&0xFu; v[2]=(unsigned)(int)a.z&0xFu; v[3]=(unsigned)(int)a.w&0xFu;
        v[4]=(unsigned)(int)b.x&0xFu; v[5]=(unsigned)(int)b.y&0xFu; v[6]=(unsigned)(int)b.z&0xFu; v[7]=(unsigned)(int)b.w&0xFu;
    } else if (m == MODE_I64) {
        const unsigned* p = (const unsigned*)xv;
#pragma unroll
        for (int e = 0; e < 8; e++) v[e] = p[2*(base+e)] & 0xFu;
    } else if (m == MODE_F64) {
        const double* p = (const double*)xv;
#pragma unroll
        for (int e = 0; e < 8; e++) v[e] = (unsigned)(int)p[base+e] & 0xFu;
    } else { // BF16
        const unsigned short* p = (const unsigned short*)xv;
#pragma unroll
        for (int e = 0; e < 8; e++)
            v[e] = (unsigned)(int)__uint_as_float((unsigned)p[base+e] << 16) & 0xFu;
    }
    unsigned long long w = 0;
#pragma unroll
    for (int e = 0; e < 8; e++) w |= ((unsigned long long)v[e]) << (8*e);
    ((unsigned long long*)g_x8)[gid] = w;
    int wp = (t >> 5) * NC;
#pragma unroll
    for (int e = 0; e < 8; e++) atomicAdd(&wb[wp + (int)v[e]], 1);
    __syncthreads();
    if (t < NC) {
        int s = 0;
#pragma unroll
        for (int k = 0; k < 8; k++) s += wb[k*NC + t];
        g_rowhist[row*NC + t] = s;
        rh[t] = s;
    }
    __syncthreads();
    if (t == 0) g_hash[row] = fnv16_sm(rh);
}

// ---------------- k_colhist: R13 8x16 body + row dup-check + col hash/check --
// grid (8,16). y==0 blocks additionally insert the 2048 row hashes into the
// dup table. The 16th finishing block per column group computes col hashes and
// inserts them too.
__global__ void k_colhist() {
    __shared__ unsigned char sb[NC*256];
    __shared__ int fin;
    int t = threadIdx.x;
#pragma unroll
    for (int c = 0; c < NC; c++) sb[c*256 + t] = 0;
    __syncthreads();
    int j  = blockIdx.x*256 + t;
    if (blockIdx.y == 0)                       // row-hash duplicate check (j == row here)
        dup_insert(__ldcg(&g_hash[j]), 0);
    int r0 = blockIdx.y * (NN/16);
    for (int r = r0; r < r0 + NN/16; r++) {
        int v = g_x8[r*NN + j];
        sb[v*256 + t]++;
    }
#pragma unroll
    for (int c = 0; c < NC; c++) {
        int cnt = sb[c*256 + t];
        if (cnt) atomicAdd(&g_colhist[j*NC + c], cnt);
    }
    __threadfence();
    __syncthreads();
    if (t == 0) {
        unsigned old = atomicAdd(&g_ccnt[blockIdx.x], 1u);
        fin = (old == 15u);
    }
    __syncthreads();
    if (fin) {
        __threadfence();
        unsigned long long h = fnv16_cg(&g_colhist[j*NC]);
        g_hash[NN + j] = h;
        dup_insert(h, 1);                       // col-hash duplicate check
    }
}

// ---------------- k_out: fast write OR full exact slow path ----------------
// 512 blocks x 256 threads, 4 blocks/SM guaranteed => co-resident => the
// monotonic grid barriers below are deadlock-free and replay-safe.
__device__ __forceinline__ void gsync(int id) {
    __syncthreads();
    if (threadIdx.x == 0) {
        __threadfence();
        unsigned old = atomicAdd(&g_sync[id], 1u);
        unsigned target = old - (old % GRID_S) + GRID_S;
        while (*(volatile unsigned*)&g_sync[id] < target) { __nanosleep(64); }
        __threadfence();
    }
    __syncthreads();
}
__global__ void __launch_bounds__(256, 4) k_out(float* __restrict__ out) {
    int t = threadIdx.x, b = blockIdx.x;
    int cbase = b*CHUNK;
    if (g_fast) {
        // out[p] = p: all hists distinct => every key unique => rank == index.
#pragma unroll
        for (int k = 0; k < 8; k++) {
            int p = cbase + k*1024 + t*4;
            *(float4*)(out + p) = make_float4((float)p, (float)(p+1), (float)(p+2), (float)(p+3));
        }
        return;
    }
    // ---- exact slow path (hash collision or genuine duplicate hists) ----
    __shared__ int red[256];
    __shared__ int ws[8], wo[8];
    // classes: 8 units per block (4096 total)
    for (int u = 0; u < 8; u++) {
        int unit = b*8 + u;
        int i = unit & (NN-1), isCol = unit >> 11;
        const unsigned long long* H = g_hash + isCol*NN;
        const int* hist = isCol ? g_colhist : g_rowhist;
        unsigned long long hi = __ldcg(&H[i]);
        int best = i;
        for (int j = t; j < i; j += 256) {
            if (__ldcg(&H[j]) == hi) {
                bool eq = true;
#pragma unroll
                for (int c = 0; c < NC; c++)
                    eq = eq && (__ldcg(&hist[j*NC + c]) == __ldcg(&hist[i*NC + c]));
                if (eq && j < best) best = j;
            }
        }
        red[t] = best;
        __syncthreads();
        for (int s = 128; s; s >>= 1) {
            if (t < s) red[t] = min(red[t], red[t+s]);
            __syncthreads();
        }
        if (t == 0) (isCol ? g_cclass : g_rclass)[i] = red[0];
        __syncthreads();
    }
    gsync(0);
    for (int p = cbase + t; p < cbase + CHUNK; p += 256)
        g_table[cell_key(p)] = 0xFFFFFFFFu;
    gsync(1);
    for (int p = cbase + t; p < cbase + CHUNK; p += 256)
        atomicMin(&g_table[cell_key(p)], (unsigned)p);
    gsync(2);
    {
        int carry = 0;
        for (int sub = 0; sub < 2; sub++) {
            int base = cbase + sub*4096 + t*16;
            int f[16], s = 0;
#pragma unroll
            for (int e = 0; e < 16; e++) {
                int p = base + e;
                f[e] = (__ldcg(&g_table[cell_key(p)]) == (unsigned)p);
                s += f[e];
            }
            int lane = t & 31, warp = t >> 5;
            int v = s;
#pragma unroll
            for (int o = 1; o < 32; o <<= 1) {
                int nv = __shfl_up_sync(0xffffffffu, v, o);
                if (lane >= o) v += nv;
            }
            if (lane == 31) ws[warp] = v;
            __syncthreads();
            if (t < 8) {
                int w = ws[t];
#pragma unroll
                for (int o = 1; o < 8; o <<= 1) {
                    int nv = __shfl_up_sync(0xffu, w, o);
                    if (t >= o) w += nv;
                }
                wo[t] = w;
            }
            __syncthreads();
            int ex = (v - s) + (warp ? wo[warp-1] : 0);
            int run = carry + ex;
#pragma unroll
            for (int e = 0; e < 16; e++) { g_scan[base + e] = run; run += f[e]; }
            carry += wo[7];
            __syncthreads();
        }
        if (t == 0) g_bsums[b] = carry;
    }
    gsync(3);
    if (b == 0 && t == 0) {
        int acc = 0;
        for (int q = 0; q < GRID_S; q++) {
            int s = g_bsums[q];
            g_bsums[q] = acc;
            acc += s;
        }
    }
    gsync(4);
    for (int p = cbase + t; p < cbase + CHUNK; p += 256) {
        unsigned q = __ldcg(&g_table[cell_key(p)]);
        out[p] = (float)(__ldcg(&g_scan[q]) + __ldcg(&g_bsums[q >> 13]));
    }
}

// ---------------- launch (3 kernels) ----------------
extern "C" void kernel_launch(void* const* d_in, const int* in_sizes, int n_in,
                              void* d_out, int out_size) {
    const void* x = d_in[0];
    (void)in_sizes; (void)n_in; (void)out_size;

    k_convert <<<NN, 256>>>(x);
    k_colhist <<<dim3(8, 16), 256>>>();
    k_out     <<<GRID_S, 256>>>((float*)d_out);
}